// round 11
// baseline (speedup 1.0000x reference)
#include <cuda_runtime.h>
#include <cuda_bf16.h>
#include <stdint.h>
#include <math.h>

#define B_ 1024
#define T_ 250
#define D_ 158
#define H_ 128
#define G_ 512
#define M_ (B_*T_)
#define P_ 64
#define O_ 22
#define KP0 192
#define KP1 128

typedef unsigned long long ull;
typedef __nv_bfloat16 bf16;

// ---------------- scratch ----------------
__device__ float g_xn[(size_t)M_ * D_];        // layer-1 h fp32 (time-major), M*128 <= M*158
__device__ float g_xg[(size_t)M_ * G_];        // gate preactivations fp32 (time-major)
__device__ bf16  g_ah[(size_t)M_ * KP0];       // A hi split (layer0 M x 192; layer1 reuse M x 128)
__device__ bf16  g_al[(size_t)M_ * KP0];
__device__ bf16  g_wh0[G_ * KP0], g_wl0[G_ * KP0];
__device__ bf16  g_wh1[G_ * KP1], g_wl1[G_ * KP1];

// ---------------- f32x2 helpers ----------------
__device__ __forceinline__ void fma2(ull& d, ull a, ull b, ull c) {
    asm("fma.rn.f32x2 %0, %1, %2, %3;" : "=l"(d) : "l"(a), "l"(b), "l"(c));
}
__device__ __forceinline__ ull pack2(float a, float b) {
    ull r; asm("mov.b64 %0, {%1,%2};" : "=l"(r) : "f"(a), "f"(b)); return r;
}
__device__ __forceinline__ uint32_t s2u(const void* p) {
    return (uint32_t)__cvta_generic_to_shared(p);
}
__device__ __forceinline__ void st_remote_u64(uint32_t laddr, uint32_t peer, ull v) {
    uint32_t r;
    asm volatile("mapa.shared::cluster.u32 %0, %1, %2;" : "=r"(r) : "r"(laddr), "r"(peer));
    asm volatile("st.shared::cluster.b64 [%0], %1;" :: "r"(r), "l"(v) : "memory");
}

// ---------------- warp-level tensor helpers (baseline PTX, works on sm_103 plain) ----------------
__device__ __forceinline__ void ldsm4(uint32_t* r, uint32_t addr) {
    asm volatile("ldmatrix.sync.aligned.m8n8.x4.shared.b16 {%0,%1,%2,%3}, [%4];"
                 : "=r"(r[0]), "=r"(r[1]), "=r"(r[2]), "=r"(r[3]) : "r"(addr));
}
__device__ __forceinline__ void mma16816(float* d, const uint32_t* a, const uint32_t* b) {
    asm volatile("mma.sync.aligned.m16n8k16.row.col.f32.bf16.bf16.f32 "
                 "{%0,%1,%2,%3}, {%4,%5,%6,%7}, {%8,%9}, {%0,%1,%2,%3};"
                 : "+f"(d[0]), "+f"(d[1]), "+f"(d[2]), "+f"(d[3])
                 : "r"(a[0]), "r"(a[1]), "r"(a[2]), "r"(a[3]), "r"(b[0]), "r"(b[1]));
}

// ---------------- activations ----------------
__device__ __forceinline__ float sigm_(float x) { return 1.f / (1.f + __expf(-x)); }
__device__ __forceinline__ float tanh_fast(float x) {
    float a = fabsf(x);
    float e = __expf(a + a);
    float t = 1.f - 2.f / (e + 1.f);
    return copysignf(t, x);
}
__device__ __forceinline__ void bf_split(float v, bf16& h, bf16& l) {
    h = __float2bfloat16_rn(v);
    l = __float2bfloat16_rn(v - __bfloat162float(h));
}

// ---------------- W split: [512][K] fp32 -> hi/lo bf16 [512][KPAD] ----------------
template <int K, int KPAD>
__global__ void wsplit_kernel(const float* __restrict__ W, bf16* __restrict__ wh,
                              bf16* __restrict__ wl) {
    int idx = blockIdx.x * 256 + threadIdx.x;
    if (idx >= G_ * KPAD) return;
    int g = idx / KPAD, k = idx - g * KPAD;
    float v = (k < K) ? W[g * K + k] : 0.f;
    bf16 h, l; bf_split(v, h, l);
    wh[idx] = h; wl[idx] = l;
}

// ---------------- LayerNorm -> bf16 hi/lo, time-major [t*B+b][KP0] ----------------
__global__ void __launch_bounds__(256) ln_split_kernel(const float* __restrict__ x,
                                                       const float* __restrict__ gamma,
                                                       const float* __restrict__ beta,
                                                       bf16* __restrict__ ah,
                                                       bf16* __restrict__ al) {
    int row_in = blockIdx.x * 8 + (threadIdx.x >> 5);   // b*T + t
    int lane = threadIdx.x & 31;
    int b = row_in / T_;
    int t = row_in - b * T_;
    const float* xr = x + (size_t)row_in * D_;
    float v[5];
    float s = 0.f, s2 = 0.f;
#pragma unroll
    for (int i = 0; i < 5; i++) {
        int k = lane + 32 * i;
        v[i] = (k < D_) ? xr[k] : 0.f;
        s += v[i];
        s2 = fmaf(v[i], v[i], s2);
    }
#pragma unroll
    for (int o = 16; o; o >>= 1) {
        s  += __shfl_xor_sync(0xffffffffu, s, o);
        s2 += __shfl_xor_sync(0xffffffffu, s2, o);
    }
    float mu  = s * (1.f / D_);
    float var = s2 * (1.f / D_) - mu * mu;
    float inv = rsqrtf(var + 1e-5f);
    size_t orow = ((size_t)t * B_ + b) * KP0;
#pragma unroll
    for (int i = 0; i < 5; i++) {
        int k = lane + 32 * i;
        float xv = (k < D_) ? ((v[i] - mu) * inv * gamma[k] + beta[k]) : 0.f;
        bf16 h, l; bf_split(xv, h, l);
        if (k < 160) { ah[orow + k] = h; al[orow + k] = l; }
    }
    ah[orow + 160 + lane] = __float2bfloat16_rn(0.f);
    al[orow + 160 + lane] = __float2bfloat16_rn(0.f);
}

// ---------------- split-bf16 mma.sync GEMM: C[M,512] = A*W^T + bias ----------------
// CTA 128m x 64n, 8 warps (4m x 2n), warp 32x32, BK=64 chunks, XOR-swizzled smem.
// D = Ah*Wh + Ah*Wl + Al*Wh  (error ~2^-16 relative)
#define GEMM_SMEM (16384 + 16384 + 8192 + 8192)
template <int KPAD>
__global__ void __launch_bounds__(256) mma_gemm_kernel(const bf16* __restrict__ Ah,
                                                       const bf16* __restrict__ Al,
                                                       const bf16* __restrict__ Wh,
                                                       const bf16* __restrict__ Wl,
                                                       const float* __restrict__ bias,
                                                       float* __restrict__ C) {
    extern __shared__ char sm2[];
    bf16* sAh = (bf16*)sm2;                 // [128][64] swizzled
    bf16* sAl = (bf16*)(sm2 + 16384);
    bf16* sWh = (bf16*)(sm2 + 32768);       // [64][64] swizzled
    bf16* sWl = (bf16*)(sm2 + 40960);

    int tid = threadIdx.x;
    int wid = tid >> 5, lane = tid & 31;
    int wm = wid & 3, wn = wid >> 2;
    int m0 = blockIdx.y * 128, n0 = blockIdx.x * 64;

    float acc[2][4][4];
#pragma unroll
    for (int i = 0; i < 2; i++)
#pragma unroll
        for (int j = 0; j < 4; j++)
#pragma unroll
            for (int q = 0; q < 4; q++) acc[i][j][q] = 0.f;

    float2 bv[4];
#pragma unroll
    for (int nt = 0; nt < 4; nt++) {
        int col = n0 + wn * 32 + nt * 8 + 2 * (lane & 3);
        bv[nt] = make_float2(bias[col], bias[col + 1]);
    }

    // precomputed ldmatrix lane geometry
    int a_row = (lane & 7) + ((lane >> 3) & 1) * 8;   // within m16 tile
    int a_chk = lane >> 4;                            // 0/1 -> k chunk
    int w_row = (lane & 7) + (lane >> 4) * 8;         // within n16 group
    int w_chk = (lane >> 3) & 1;

    for (int kc = 0; kc < KPAD / 64; kc++) {
        __syncthreads();
        {
            const bf16* gA0 = Ah + (size_t)m0 * KPAD + kc * 64;
            const bf16* gA1 = Al + (size_t)m0 * KPAD + kc * 64;
#pragma unroll 2
            for (int i = tid; i < 1024; i += 256) {
                int row = i >> 3, c = i & 7;
                int phys = c ^ (row & 7);
                *(uint4*)(sAh + row * 64 + phys * 8) = *(const uint4*)(gA0 + (size_t)row * KPAD + c * 8);
                *(uint4*)(sAl + row * 64 + phys * 8) = *(const uint4*)(gA1 + (size_t)row * KPAD + c * 8);
            }
            const bf16* gW0 = Wh + (size_t)n0 * KPAD + kc * 64;
            const bf16* gW1 = Wl + (size_t)n0 * KPAD + kc * 64;
#pragma unroll 1
            for (int i = tid; i < 512; i += 256) {
                int row = i >> 3, c = i & 7;
                int phys = c ^ (row & 7);
                *(uint4*)(sWh + row * 64 + phys * 8) = *(const uint4*)(gW0 + (size_t)row * KPAD + c * 8);
                *(uint4*)(sWl + row * 64 + phys * 8) = *(const uint4*)(gW1 + (size_t)row * KPAD + c * 8);
            }
        }
        __syncthreads();

#pragma unroll
        for (int ks = 0; ks < 4; ks++) {
            int cb = ks * 2;
            uint32_t ah[2][4], al[2][4], wh[4][2], wl[4][2];
#pragma unroll
            for (int mt = 0; mt < 2; mt++) {
                int row = wm * 32 + mt * 16 + a_row;
                int chk = cb + a_chk;
                uint32_t off = (uint32_t)(row * 64 + (chk ^ (row & 7)) * 8) * 2u;
                ldsm4(ah[mt], s2u(sAh) + off);
                ldsm4(al[mt], s2u(sAl) + off);
            }
#pragma unroll
            for (int g = 0; g < 2; g++) {
                int row = wn * 32 + g * 16 + w_row;
                int chk = cb + w_chk;
                uint32_t off = (uint32_t)(row * 64 + (chk ^ (row & 7)) * 8) * 2u;
                uint32_t rh[4], rl[4];
                ldsm4(rh, s2u(sWh) + off);
                ldsm4(rl, s2u(sWl) + off);
                wh[2 * g][0] = rh[0]; wh[2 * g][1] = rh[1];
                wh[2 * g + 1][0] = rh[2]; wh[2 * g + 1][1] = rh[3];
                wl[2 * g][0] = rl[0]; wl[2 * g][1] = rl[1];
                wl[2 * g + 1][0] = rl[2]; wl[2 * g + 1][1] = rl[3];
            }
#pragma unroll
            for (int mt = 0; mt < 2; mt++)
#pragma unroll
                for (int nt = 0; nt < 4; nt++) {
                    mma16816(acc[mt][nt], ah[mt], wh[nt]);
                    mma16816(acc[mt][nt], ah[mt], wl[nt]);
                    mma16816(acc[mt][nt], al[mt], wh[nt]);
                }
        }
    }

    // epilogue: direct float2 stores with bias
#pragma unroll
    for (int mt = 0; mt < 2; mt++) {
        int row = m0 + wm * 32 + mt * 16 + (lane >> 2);
#pragma unroll
        for (int nt = 0; nt < 4; nt++) {
            int col = n0 + wn * 32 + nt * 8 + 2 * (lane & 3);
            float* p = C + (size_t)row * G_ + col;
            *(float2*)p = make_float2(acc[mt][nt][0] + bv[nt].x, acc[mt][nt][1] + bv[nt].y);
            *(float2*)(p + 8 * G_) = make_float2(acc[mt][nt][2] + bv[nt].x, acc[mt][nt][3] + bv[nt].y);
        }
    }
}

// ---------------- clustered LSTM: warp<->gates, lanes<->rows ----------------
// smem: ws 128*128 ull (128KB) + hs [2][128][17] ull (34.8KB) + gs [16][258] f32 (16.5KB)
#define LSTM_SMEM (131072 + 2*128*17*8 + 16*258*4)

template <int OUTBF>
__global__ void __launch_bounds__(256) __cluster_dims__(2, 1, 1)
lstm_cluster_kernel(const float* __restrict__ xg,        // time-major [t*B+b][512]
                    const float* __restrict__ Whh,
                    float* __restrict__ houtf,           // OUTBF=0: fp32 [t*B+b][128]
                    bf16* __restrict__ ah,               // OUTBF=1: hi/lo bf16
                    bf16* __restrict__ al) {
    extern __shared__ ull sm[];
    ull*   ws = sm;                                 // [128 k][128 gate-pair]
    ull*   hs = sm + 128 * 128;                     // [2][128][17]
    float* gs = (float*)(sm + 128 * 128 + 2 * 128 * 17);   // [16][258]

    int tid = threadIdx.x;
    uint32_t crank;
    asm("mov.u32 %0, %%cluster_ctarank;" : "=r"(crank));
    int c = (int)crank;
    int b0 = (blockIdx.x >> 1) * 16;

    for (int idx = tid; idx < 128 * 128; idx += 256) {
        int k = idx >> 7, gp = idx & 127;
        int q = gp >> 5, jl = 2 * (gp & 31);
        int g0 = 128 * q + 64 * c + jl;
        ws[idx] = pack2(Whh[g0 * 128 + k], Whh[g0 * 128 + 128 + k]);
    }
    for (int i = tid; i < 2 * 128 * 17; i += 256) hs[i] = 0ull;
    __syncthreads();
    asm volatile("barrier.cluster.arrive.aligned;" ::: "memory");
    asm volatile("barrier.cluster.wait.aligned;" ::: "memory");

    int w   = tid >> 5;
    int sub = (tid & 31) >> 4;
    int r   = tid & 15;
    int gpb = w * 16 + sub * 8;
    int lbase = w * 32 + sub * 16;
    int g0 = 128 * (w >> 1) + 64 * c + (w & 1) * 32 + sub * 16;

    int wB = tid >> 5;
    int l2 = (tid & 31) * 2;
    float2 cst[2] = {{0.f, 0.f}, {0.f, 0.f}};

    uint32_t hs_u32 = s2u(hs);
    const float* xgl = xg + (size_t)(b0 + r) * G_ + g0;
    const size_t TSTR = (size_t)B_ * G_;

    ull pr[8];
#pragma unroll
    for (int i = 0; i < 4; i++) {
        ulonglong2 p = *(const ulonglong2*)(xgl + 4 * i);
        pr[2 * i] = p.x; pr[2 * i + 1] = p.y;
    }

    for (int t = 0; t < T_; t++) {
        int par = t & 1;
        ull acc[8];
#pragma unroll
        for (int i = 0; i < 8; i++) acc[i] = pr[i];
        size_t tn = (size_t)((t + 1 < T_) ? (t + 1) : t) * TSTR;
#pragma unroll
        for (int i = 0; i < 4; i++) {
            ulonglong2 p = *(const ulonglong2*)(xgl + tn + 4 * i);
            pr[2 * i] = p.x; pr[2 * i + 1] = p.y;
        }

        const ull* hp = hs + par * (128 * 17) + r;
        const ulonglong2* wp = (const ulonglong2*)(ws + gpb);
#pragma unroll 4
        for (int k = 0; k < H_; k++) {
            ulonglong2 w01 = wp[k * 64];
            ulonglong2 w23 = wp[k * 64 + 1];
            ulonglong2 w45 = wp[k * 64 + 2];
            ulonglong2 w67 = wp[k * 64 + 3];
            ull hd = hp[k * 17];
            fma2(acc[0], (ull)w01.x, hd, acc[0]);
            fma2(acc[1], (ull)w01.y, hd, acc[1]);
            fma2(acc[2], (ull)w23.x, hd, acc[2]);
            fma2(acc[3], (ull)w23.y, hd, acc[3]);
            fma2(acc[4], (ull)w45.x, hd, acc[4]);
            fma2(acc[5], (ull)w45.y, hd, acc[5]);
            fma2(acc[6], (ull)w67.x, hd, acc[6]);
            fma2(acc[7], (ull)w67.y, hd, acc[7]);
        }
#pragma unroll
        for (int i = 0; i < 8; i++)
            *(ull*)&gs[r * 258 + lbase + 2 * i] = acc[i];
        __syncthreads();

        ull* hnew = hs + (par ^ 1) * (128 * 17);
        uint32_t hnew_u32 = hs_u32 + (uint32_t)((par ^ 1) * (128 * 17)) * 8u;
#pragma unroll
        for (int s = 0; s < 2; s++) {
            int row = wB + 8 * s;
            float2 gi = *(float2*)&gs[row * 258 + l2];
            float2 gf = *(float2*)&gs[row * 258 + 64 + l2];
            float2 gg = *(float2*)&gs[row * 258 + 128 + l2];
            float2 go = *(float2*)&gs[row * 258 + 192 + l2];
            float2 cc = cst[s];
            cc.x = sigm_(gf.x) * cc.x + sigm_(gi.x) * tanh_fast(gg.x);
            cc.y = sigm_(gf.y) * cc.y + sigm_(gi.y) * tanh_fast(gg.y);
            float h0v = sigm_(go.x) * tanh_fast(cc.x);
            float h1v = sigm_(go.y) * tanh_fast(cc.y);
            cst[s] = cc;
            int jj = 64 * c + l2;
            ull p0 = pack2(h0v, h0v), p1 = pack2(h1v, h1v);
            hnew[jj * 17 + row]       = p0;
            hnew[(jj + 1) * 17 + row] = p1;
            st_remote_u64(hnew_u32 + (uint32_t)(jj * 17 + row) * 8u, (uint32_t)(c ^ 1), p0);
            st_remote_u64(hnew_u32 + (uint32_t)((jj + 1) * 17 + row) * 8u, (uint32_t)(c ^ 1), p1);
            size_t orow = ((size_t)t * B_ + b0 + row) * H_ + jj;
            if (OUTBF) {
                bf16 h0h, h0l, h1h, h1l;
                bf_split(h0v, h0h, h0l);
                bf_split(h1v, h1h, h1l);
                __nv_bfloat162 hh; hh.x = h0h; hh.y = h1h;
                __nv_bfloat162 ll; ll.x = h0l; ll.y = h1l;
                *(__nv_bfloat162*)&ah[orow] = hh;
                *(__nv_bfloat162*)&al[orow] = ll;
            } else {
                *(float2*)&houtf[orow] = make_float2(h0v, h1v);
            }
        }
        asm volatile("barrier.cluster.arrive.aligned;" ::: "memory");
        asm volatile("barrier.cluster.wait.aligned;" ::: "memory");
    }
}

// ---------------- projection head (time-major in, [b][t] out) ----------------
__global__ void __launch_bounds__(256) proj_kernel(const float* __restrict__ h,
                                                   const float* __restrict__ Wp1,
                                                   const float* __restrict__ bp1,
                                                   const float* __restrict__ Wp2,
                                                   const float* __restrict__ bp2,
                                                   float* __restrict__ out) {
    __shared__ float w1t[128][65];
    __shared__ float w2t[64][22];
    __shared__ float ps[32][64];
    __shared__ float b1s[64];
    __shared__ float b2s[22];
    int tid = threadIdx.x;

    for (int i = tid; i < P_ * H_; i += 256) { int jj = i >> 7, kk = i & 127; w1t[kk][jj] = Wp1[i]; }
    for (int i = tid; i < O_ * P_; i += 256) { int oo = i >> 6, kk = i & 63;  w2t[kk][oo] = Wp2[i]; }
    if (tid < P_) b1s[tid] = bp1[tid];
    if (tid < O_) b2s[tid] = bp2[tid];
    __syncthreads();

    size_t row0 = (size_t)blockIdx.x * 32;
    int tt  = (int)(row0 >> 10);
    int bb0 = (int)(row0 & 1023);
    int jj = tid & 63;
    int rs = tid >> 6;
    float acc[8] = {};
    const float* hrow[8];
#pragma unroll
    for (int rr = 0; rr < 8; rr++) hrow[rr] = h + (row0 + (size_t)rs * 8 + rr) * H_;

    for (int k4 = 0; k4 < 32; k4++) {
        float4 hv[8];
#pragma unroll
        for (int rr = 0; rr < 8; rr++) hv[rr] = *(const float4*)(hrow[rr] + 4 * k4);
#pragma unroll
        for (int kk = 0; kk < 4; kk++) {
            float w = w1t[4 * k4 + kk][jj];
#pragma unroll
            for (int rr = 0; rr < 8; rr++) {
                float hvv = (&hv[rr].x)[kk];
                acc[rr] = fmaf(hvv, w, acc[rr]);
            }
        }
    }
#pragma unroll
    for (int rr = 0; rr < 8; rr++) {
        float v = acc[rr] + b1s[jj];
        ps[rs * 8 + rr][jj] = v > 0.f ? v : 0.f;
    }
    __syncthreads();

    for (int idx = tid; idx < 32 * O_; idx += 256) {
        int rr = idx / O_;
        int oo = idx - rr * O_;
        float s = b2s[oo];
#pragma unroll
        for (int k = 0; k < P_; k++) s = fmaf(ps[rr][k], w2t[k][oo], s);
        out[((size_t)(bb0 + rr) * T_ + tt) * O_ + oo] = s;
    }
}

// ---------------- launch ----------------
extern "C" void kernel_launch(void* const* d_in, const int* in_sizes, int n_in,
                              void* d_out, int out_size) {
    const float* x     = (const float*)d_in[0];
    const float* ln_g  = (const float*)d_in[1];
    const float* ln_b  = (const float*)d_in[2];
    const float* W_ih0 = (const float*)d_in[3];
    const float* W_hh0 = (const float*)d_in[4];
    const float* b0    = (const float*)d_in[5];
    const float* W_ih1 = (const float*)d_in[6];
    const float* W_hh1 = (const float*)d_in[7];
    const float* b1    = (const float*)d_in[8];
    const float* Wp1   = (const float*)d_in[9];
    const float* bp1   = (const float*)d_in[10];
    const float* Wp2   = (const float*)d_in[11];
    const float* bp2   = (const float*)d_in[12];
    float* out = (float*)d_out;

    float *xn, *xg;
    bf16 *ah, *al, *wh0, *wl0, *wh1, *wl1;
    cudaGetSymbolAddress((void**)&xn,  g_xn);
    cudaGetSymbolAddress((void**)&xg,  g_xg);
    cudaGetSymbolAddress((void**)&ah,  g_ah);
    cudaGetSymbolAddress((void**)&al,  g_al);
    cudaGetSymbolAddress((void**)&wh0, g_wh0);
    cudaGetSymbolAddress((void**)&wl0, g_wl0);
    cudaGetSymbolAddress((void**)&wh1, g_wh1);
    cudaGetSymbolAddress((void**)&wl1, g_wl1);

    cudaFuncSetAttribute(mma_gemm_kernel<KP0>, cudaFuncAttributeMaxDynamicSharedMemorySize, GEMM_SMEM);
    cudaFuncSetAttribute(mma_gemm_kernel<KP1>, cudaFuncAttributeMaxDynamicSharedMemorySize, GEMM_SMEM);
    cudaFuncSetAttribute(lstm_cluster_kernel<1>, cudaFuncAttributeMaxDynamicSharedMemorySize, LSTM_SMEM);
    cudaFuncSetAttribute(lstm_cluster_kernel<0>, cudaFuncAttributeMaxDynamicSharedMemorySize, LSTM_SMEM);

    wsplit_kernel<D_, KP0><<<(G_ * KP0 + 255) / 256, 256>>>(W_ih0, wh0, wl0);
    wsplit_kernel<H_, KP1><<<(G_ * KP1 + 255) / 256, 256>>>(W_ih1, wh1, wl1);
    ln_split_kernel<<<M_ / 8, 256>>>(x, ln_g, ln_b, ah, al);

    mma_gemm_kernel<KP0><<<dim3(8, M_ / 128), 256, GEMM_SMEM>>>(ah, al, wh0, wl0, b0, xg);
    lstm_cluster_kernel<1><<<128, 256, LSTM_SMEM>>>(xg, W_hh0, nullptr, ah, al);

    mma_gemm_kernel<KP1><<<dim3(8, M_ / 128), 256, GEMM_SMEM>>>(ah, al, wh1, wl1, b1, xg);
    lstm_cluster_kernel<0><<<128, 256, LSTM_SMEM>>>(xg, W_hh1, xn, nullptr, nullptr);

    proj_kernel<<<M_ / 32, 256>>>(xn, Wp1, bp1, Wp2, bp2, out);
}

// round 14
// speedup vs baseline: 1.8686x; 1.8686x over previous
#include <cuda_runtime.h>
#include <cuda_bf16.h>
#include <stdint.h>
#include <math.h>

#define B_ 1024
#define T_ 250
#define D_ 158
#define H_ 128
#define G_ 512
#define M_ (B_*T_)
#define P_ 64
#define O_ 22
#define KP0 192
#define KP1 128

typedef unsigned long long ull;
typedef __nv_bfloat16 bf16;

// ---------------- scratch ----------------
__device__ float g_xn[(size_t)M_ * H_];        // layer-1 h fp32 (batch-major)
__device__ float g_h0[(size_t)M_ * H_];        // layer-0 h fp32
__device__ float g_xg[(size_t)M_ * G_];        // gate preactivations fp32
__device__ bf16  g_ah[(size_t)M_ * KP0];       // A hi split
__device__ bf16  g_al[(size_t)M_ * KP0];
__device__ bf16  g_wh0[G_ * KP0], g_wl0[G_ * KP0];
__device__ bf16  g_wh1[G_ * KP1], g_wl1[G_ * KP1];

// ---------------- f32x2 helpers ----------------
__device__ __forceinline__ void fma2(ull& d, ull a, ull b, ull c) {
    asm("fma.rn.f32x2 %0, %1, %2, %3;" : "=l"(d) : "l"(a), "l"(b), "l"(c));
}
__device__ __forceinline__ ull pack2(float a, float b) {
    ull r; asm("mov.b64 %0, {%1,%2};" : "=l"(r) : "f"(a), "f"(b)); return r;
}
__device__ __forceinline__ uint32_t s2u(const void* p) {
    return (uint32_t)__cvta_generic_to_shared(p);
}
__device__ __forceinline__ void st_remote_u64(uint32_t laddr, uint32_t peer, ull v) {
    uint32_t r;
    asm volatile("mapa.shared::cluster.u32 %0, %1, %2;" : "=r"(r) : "r"(laddr), "r"(peer));
    asm volatile("st.shared::cluster.b64 [%0], %1;" :: "r"(r), "l"(v) : "memory");
}

// ---------------- warp-level tensor helpers (baseline PTX, sm_103-plain safe) ----------------
__device__ __forceinline__ void ldsm4(uint32_t* r, uint32_t addr) {
    asm volatile("ldmatrix.sync.aligned.m8n8.x4.shared.b16 {%0,%1,%2,%3}, [%4];"
                 : "=r"(r[0]), "=r"(r[1]), "=r"(r[2]), "=r"(r[3]) : "r"(addr));
}
__device__ __forceinline__ void mma16816(float* d, const uint32_t* a, const uint32_t* b) {
    asm volatile("mma.sync.aligned.m16n8k16.row.col.f32.bf16.bf16.f32 "
                 "{%0,%1,%2,%3}, {%4,%5,%6,%7}, {%8,%9}, {%0,%1,%2,%3};"
                 : "+f"(d[0]), "+f"(d[1]), "+f"(d[2]), "+f"(d[3])
                 : "r"(a[0]), "r"(a[1]), "r"(a[2]), "r"(a[3]), "r"(b[0]), "r"(b[1]));
}

// ---------------- activations ----------------
__device__ __forceinline__ float sigm_(float x) { return 1.f / (1.f + __expf(-x)); }
__device__ __forceinline__ float tanh_fast(float x) {
    float a = fabsf(x);
    float e = __expf(a + a);
    float t = 1.f - 2.f / (e + 1.f);
    return copysignf(t, x);
}
__device__ __forceinline__ void bf_split(float v, bf16& h, bf16& l) {
    h = __float2bfloat16_rn(v);
    l = __float2bfloat16_rn(v - __bfloat162float(h));
}

// ---------------- W split: [512][K] fp32 -> hi/lo bf16 [512][KPAD] ----------------
template <int K, int KPAD>
__global__ void wsplit_kernel(const float* __restrict__ W, bf16* __restrict__ wh,
                              bf16* __restrict__ wl) {
    int idx = blockIdx.x * 256 + threadIdx.x;
    if (idx >= G_ * KPAD) return;
    int g = idx / KPAD, k = idx - g * KPAD;
    float v = (k < K) ? W[g * K + k] : 0.f;
    bf16 h, l; bf_split(v, h, l);
    wh[idx] = h; wl[idx] = l;
}

// ---------------- h split: [M][128] fp32 -> hi/lo bf16 ----------------
__global__ void __launch_bounds__(256) hsplit_kernel(const float* __restrict__ h,
                                                     bf16* __restrict__ ah,
                                                     bf16* __restrict__ al) {
    size_t idx = (size_t)blockIdx.x * 512 + threadIdx.x * 2;
    float2 v = *(const float2*)(h + idx);
    bf16 h0, l0, h1, l1;
    bf_split(v.x, h0, l0);
    bf_split(v.y, h1, l1);
    __nv_bfloat162 hh; hh.x = h0; hh.y = h1;
    __nv_bfloat162 ll; ll.x = l0; ll.y = l1;
    *(__nv_bfloat162*)(ah + idx) = hh;
    *(__nv_bfloat162*)(al + idx) = ll;
}

// ---------------- LayerNorm -> bf16 hi/lo, batch-major [b*T+t][KP0] ----------------
__global__ void __launch_bounds__(256) ln_split_kernel(const float* __restrict__ x,
                                                       const float* __restrict__ gamma,
                                                       const float* __restrict__ beta,
                                                       bf16* __restrict__ ah,
                                                       bf16* __restrict__ al) {
    int row = blockIdx.x * 8 + (threadIdx.x >> 5);
    int lane = threadIdx.x & 31;
    const float* xr = x + (size_t)row * D_;
    float v[5];
    float s = 0.f, s2 = 0.f;
#pragma unroll
    for (int i = 0; i < 5; i++) {
        int k = lane + 32 * i;
        v[i] = (k < D_) ? xr[k] : 0.f;
        s += v[i];
        s2 = fmaf(v[i], v[i], s2);
    }
#pragma unroll
    for (int o = 16; o; o >>= 1) {
        s  += __shfl_xor_sync(0xffffffffu, s, o);
        s2 += __shfl_xor_sync(0xffffffffu, s2, o);
    }
    float mu  = s * (1.f / D_);
    float var = s2 * (1.f / D_) - mu * mu;
    float inv = rsqrtf(var + 1e-5f);
    size_t orow = (size_t)row * KP0;
#pragma unroll
    for (int i = 0; i < 5; i++) {
        int k = lane + 32 * i;
        float xv = (k < D_) ? ((v[i] - mu) * inv * gamma[k] + beta[k]) : 0.f;
        bf16 h, l; bf_split(xv, h, l);
        if (k < 160) { ah[orow + k] = h; al[orow + k] = l; }
    }
    ah[orow + 160 + lane] = __float2bfloat16_rn(0.f);
    al[orow + 160 + lane] = __float2bfloat16_rn(0.f);
}

// ---------------- split-bf16 mma.sync GEMM (validated R11): C[M,512]=A*W^T+bias ----------------
#define GEMM_SMEM (16384 + 16384 + 8192 + 8192)
template <int KPAD>
__global__ void __launch_bounds__(256) mma_gemm_kernel(const bf16* __restrict__ Ah,
                                                       const bf16* __restrict__ Al,
                                                       const bf16* __restrict__ Wh,
                                                       const bf16* __restrict__ Wl,
                                                       const float* __restrict__ bias,
                                                       float* __restrict__ C) {
    extern __shared__ char sm2[];
    bf16* sAh = (bf16*)sm2;
    bf16* sAl = (bf16*)(sm2 + 16384);
    bf16* sWh = (bf16*)(sm2 + 32768);
    bf16* sWl = (bf16*)(sm2 + 40960);

    int tid = threadIdx.x;
    int wid = tid >> 5, lane = tid & 31;
    int wm = wid & 3, wn = wid >> 2;
    int m0 = blockIdx.y * 128, n0 = blockIdx.x * 64;

    float acc[2][4][4];
#pragma unroll
    for (int i = 0; i < 2; i++)
#pragma unroll
        for (int j = 0; j < 4; j++)
#pragma unroll
            for (int q = 0; q < 4; q++) acc[i][j][q] = 0.f;

    float2 bv[4];
#pragma unroll
    for (int nt = 0; nt < 4; nt++) {
        int col = n0 + wn * 32 + nt * 8 + 2 * (lane & 3);
        bv[nt] = make_float2(bias[col], bias[col + 1]);
    }

    int a_row = (lane & 7) + ((lane >> 3) & 1) * 8;
    int a_chk = lane >> 4;
    int w_row = (lane & 7) + (lane >> 4) * 8;
    int w_chk = (lane >> 3) & 1;

    for (int kc = 0; kc < KPAD / 64; kc++) {
        __syncthreads();
        {
            const bf16* gA0 = Ah + (size_t)m0 * KPAD + kc * 64;
            const bf16* gA1 = Al + (size_t)m0 * KPAD + kc * 64;
#pragma unroll 2
            for (int i = tid; i < 1024; i += 256) {
                int row = i >> 3, c = i & 7;
                int phys = c ^ (row & 7);
                *(uint4*)(sAh + row * 64 + phys * 8) = *(const uint4*)(gA0 + (size_t)row * KPAD + c * 8);
                *(uint4*)(sAl + row * 64 + phys * 8) = *(const uint4*)(gA1 + (size_t)row * KPAD + c * 8);
            }
            const bf16* gW0 = Wh + (size_t)n0 * KPAD + kc * 64;
            const bf16* gW1 = Wl + (size_t)n0 * KPAD + kc * 64;
#pragma unroll 1
            for (int i = tid; i < 512; i += 256) {
                int row = i >> 3, c = i & 7;
                int phys = c ^ (row & 7);
                *(uint4*)(sWh + row * 64 + phys * 8) = *(const uint4*)(gW0 + (size_t)row * KPAD + c * 8);
                *(uint4*)(sWl + row * 64 + phys * 8) = *(const uint4*)(gW1 + (size_t)row * KPAD + c * 8);
            }
        }
        __syncthreads();

#pragma unroll
        for (int ks = 0; ks < 4; ks++) {
            int cb = ks * 2;
            uint32_t ah[2][4], al[2][4], wh[4][2], wl[4][2];
#pragma unroll
            for (int mt = 0; mt < 2; mt++) {
                int row = wm * 32 + mt * 16 + a_row;
                int chk = cb + a_chk;
                uint32_t off = (uint32_t)(row * 64 + (chk ^ (row & 7)) * 8) * 2u;
                ldsm4(ah[mt], s2u(sAh) + off);
                ldsm4(al[mt], s2u(sAl) + off);
            }
#pragma unroll
            for (int g = 0; g < 2; g++) {
                int row = wn * 32 + g * 16 + w_row;
                int chk = cb + w_chk;
                uint32_t off = (uint32_t)(row * 64 + (chk ^ (row & 7)) * 8) * 2u;
                uint32_t rh[4], rl[4];
                ldsm4(rh, s2u(sWh) + off);
                ldsm4(rl, s2u(sWl) + off);
                wh[2 * g][0] = rh[0]; wh[2 * g][1] = rh[1];
                wh[2 * g + 1][0] = rh[2]; wh[2 * g + 1][1] = rh[3];
                wl[2 * g][0] = rl[0]; wl[2 * g][1] = rl[1];
                wl[2 * g + 1][0] = rl[2]; wl[2 * g + 1][1] = rl[3];
            }
#pragma unroll
            for (int mt = 0; mt < 2; mt++)
#pragma unroll
                for (int nt = 0; nt < 4; nt++) {
                    mma16816(acc[mt][nt], ah[mt], wh[nt]);
                    mma16816(acc[mt][nt], ah[mt], wl[nt]);
                    mma16816(acc[mt][nt], al[mt], wh[nt]);
                }
        }
    }

#pragma unroll
    for (int mt = 0; mt < 2; mt++) {
        int row = m0 + wm * 32 + mt * 16 + (lane >> 2);
#pragma unroll
        for (int nt = 0; nt < 4; nt++) {
            int col = n0 + wn * 32 + nt * 8 + 2 * (lane & 3);
            float* p = C + (size_t)row * G_ + col;
            *(float2*)p = make_float2(acc[mt][nt][0] + bv[nt].x, acc[mt][nt][1] + bv[nt].y);
            *(float2*)(p + 8 * G_) = make_float2(acc[mt][nt][2] + bv[nt].x, acc[mt][nt][3] + bv[nt].y);
        }
    }
}

// ---------------- clustered LSTM recurrence (EXACT R7 measured-good version) ----------------
// batch-major xg [b*T+t][512]; Whh [512][128]; hout [b*T+t][128] fp32
#define LSTM_SMEM_BYTES (131072 + 36864 + 16384)

__global__ void __launch_bounds__(256) __cluster_dims__(2, 1, 1)
lstm_cluster_kernel(const float* __restrict__ xg,
                    const float* __restrict__ Whh,
                    float* __restrict__ hout) {
    extern __shared__ ull sm[];
    ull*   ws  = sm;                          // 128*128 pairs
    ull*   hsb = sm + 128 * 128;              // [2][128][18]
    float* gs  = (float*)(sm + 128 * 128 + 2 * 128 * 18);   // [16][256]

    int tid = threadIdx.x;
    uint32_t crank;
    asm("mov.u32 %0, %%cluster_ctarank;" : "=r"(crank));
    int c = (int)crank;
    int b0 = (blockIdx.x >> 1) * 16;

    for (int idx = tid; idx < 128 * 128; idx += 256) {
        int k = idx >> 7, gp = idx & 127;
        int q = gp >> 5, jl = 2 * (gp & 31);
        int g0 = 128 * q + 64 * c + jl;
        ws[idx] = pack2(Whh[g0 * 128 + k], Whh[g0 * 128 + 128 + k]);
    }
    for (int i = tid; i < 2 * 128 * 18; i += 256) hsb[i] = 0ull;
    __syncthreads();
    asm volatile("barrier.cluster.arrive.aligned;" ::: "memory");
    asm volatile("barrier.cluster.wait.aligned;" ::: "memory");

    int m  = tid & 63;
    int rh = tid >> 6;
    int q  = m >> 4;
    int jb = (4 * m) & 63;
    int gbase = 128 * q + 64 * c + jb;
    int gsoff = q * 64 + jb;

    int wB = tid >> 5;
    int l  = tid & 31;
    float2 cst[2] = {{0.f, 0.f}, {0.f, 0.f}};

    uint32_t hs_u32 = s2u(hsb);
    const float* xgp[4];
#pragma unroll
    for (int r = 0; r < 4; r++)
        xgp[r] = xg + (size_t)(b0 + rh * 4 + r) * T_ * G_ + gbase;

    ulonglong2 pref[4];
#pragma unroll
    for (int r = 0; r < 4; r++) pref[r] = *(const ulonglong2*)(xgp[r]);

    for (int t = 0; t < T_; t++) {
        int par = t & 1;
        ull acc[4][2];
#pragma unroll
        for (int r = 0; r < 4; r++) { acc[r][0] = pref[r].x; acc[r][1] = pref[r].y; }
        int tn = (t + 1 < T_) ? (t + 1) : t;
#pragma unroll
        for (int r = 0; r < 4; r++)
            pref[r] = *(const ulonglong2*)(xgp[r] + (size_t)tn * G_);

        const ull* hpar = hsb + par * (128 * 18) + rh * 4;
        const ull* wsp  = ws + 2 * m;
#pragma unroll 4
        for (int k = 0; k < H_; k++) {
            ulonglong2 w2 = *(const ulonglong2*)(wsp + k * 128);
            ulonglong2 ha = *(const ulonglong2*)(hpar + k * 18);
            ulonglong2 hb = *(const ulonglong2*)(hpar + k * 18 + 2);
            fma2(acc[0][0], (ull)w2.x, (ull)ha.x, acc[0][0]);
            fma2(acc[0][1], (ull)w2.y, (ull)ha.x, acc[0][1]);
            fma2(acc[1][0], (ull)w2.x, (ull)ha.y, acc[1][0]);
            fma2(acc[1][1], (ull)w2.y, (ull)ha.y, acc[1][1]);
            fma2(acc[2][0], (ull)w2.x, (ull)hb.x, acc[2][0]);
            fma2(acc[2][1], (ull)w2.y, (ull)hb.x, acc[2][1]);
            fma2(acc[3][0], (ull)w2.x, (ull)hb.y, acc[3][0]);
            fma2(acc[3][1], (ull)w2.y, (ull)hb.y, acc[3][1]);
        }
#pragma unroll
        for (int r = 0; r < 4; r++) {
            int row = rh * 4 + r;
            *(ulonglong2*)&gs[row * 256 + gsoff] =
                make_ulonglong2((long long)acc[r][0], (long long)acc[r][1]);
        }
        __syncthreads();

        ull* hnew = hsb + (par ^ 1) * (128 * 18);
        uint32_t hnew_u32 = hs_u32 + (uint32_t)((par ^ 1) * (128 * 18)) * 8u;
#pragma unroll
        for (int s = 0; s < 2; s++) {
            int row = wB + 8 * s;
            float2 gi = *(float2*)&gs[row * 256 + 2 * l];
            float2 gf = *(float2*)&gs[row * 256 + 64 + 2 * l];
            float2 gg = *(float2*)&gs[row * 256 + 128 + 2 * l];
            float2 go = *(float2*)&gs[row * 256 + 192 + 2 * l];
            float2 cc = cst[s];
            cc.x = sigm_(gf.x) * cc.x + sigm_(gi.x) * tanh_fast(gg.x);
            cc.y = sigm_(gf.y) * cc.y + sigm_(gi.y) * tanh_fast(gg.y);
            float h0v = sigm_(go.x) * tanh_fast(cc.x);
            float h1v = sigm_(go.y) * tanh_fast(cc.y);
            cst[s] = cc;
            int j = 64 * c + 2 * l;
            ull p0 = pack2(h0v, h0v), p1 = pack2(h1v, h1v);
            hnew[(size_t)j * 18 + row]       = p0;
            hnew[(size_t)(j + 1) * 18 + row] = p1;
            uint32_t a0 = hnew_u32 + (uint32_t)(j * 18 + row) * 8u;
            st_remote_u64(a0,            (uint32_t)(c ^ 1), p0);
            st_remote_u64(a0 + 18u * 8u, (uint32_t)(c ^ 1), p1);
            *(float2*)&hout[((size_t)(b0 + row) * T_ + t) * H_ + j] = make_float2(h0v, h1v);
        }
        asm volatile("barrier.cluster.arrive.aligned;" ::: "memory");
        asm volatile("barrier.cluster.wait.aligned;" ::: "memory");
    }
}

// ---------------- projection head (R7 batch-major version) ----------------
__global__ void __launch_bounds__(256) proj_kernel(const float* __restrict__ h,
                                                   const float* __restrict__ Wp1,
                                                   const float* __restrict__ bp1,
                                                   const float* __restrict__ Wp2,
                                                   const float* __restrict__ bp2,
                                                   float* __restrict__ out) {
    __shared__ float w1t[128][65];
    __shared__ float w2t[64][22];
    __shared__ float ps[32][64];
    __shared__ float b1s[64];
    __shared__ float b2s[22];
    int tid = threadIdx.x;

    for (int i = tid; i < P_ * H_; i += 256) { int jj = i >> 7, kk = i & 127; w1t[kk][jj] = Wp1[i]; }
    for (int i = tid; i < O_ * P_; i += 256) { int oo = i >> 6, kk = i & 63;  w2t[kk][oo] = Wp2[i]; }
    if (tid < P_) b1s[tid] = bp1[tid];
    if (tid < O_) b2s[tid] = bp2[tid];
    __syncthreads();

    size_t row0 = (size_t)blockIdx.x * 32;
    int jj = tid & 63;
    int rs = tid >> 6;
    float acc[8] = {};
    const float* hrow[8];
#pragma unroll
    for (int rr = 0; rr < 8; rr++) hrow[rr] = h + (row0 + (size_t)rs * 8 + rr) * H_;

    for (int k4 = 0; k4 < 32; k4++) {
        float4 hv[8];
#pragma unroll
        for (int rr = 0; rr < 8; rr++) hv[rr] = *(const float4*)(hrow[rr] + 4 * k4);
#pragma unroll
        for (int kk = 0; kk < 4; kk++) {
            float w = w1t[4 * k4 + kk][jj];
#pragma unroll
            for (int rr = 0; rr < 8; rr++) {
                float hvv = (&hv[rr].x)[kk];
                acc[rr] = fmaf(hvv, w, acc[rr]);
            }
        }
    }
#pragma unroll
    for (int rr = 0; rr < 8; rr++) {
        float v = acc[rr] + b1s[jj];
        ps[rs * 8 + rr][jj] = v > 0.f ? v : 0.f;
    }
    __syncthreads();

    for (int idx = tid; idx < 32 * O_; idx += 256) {
        int rr = idx / O_;
        int oo = idx - rr * O_;
        float s = b2s[oo];
#pragma unroll
        for (int k = 0; k < P_; k++) s = fmaf(ps[rr][k], w2t[k][oo], s);
        out[(row0 + rr) * O_ + oo] = s;
    }
}

// ---------------- launch ----------------
extern "C" void kernel_launch(void* const* d_in, const int* in_sizes, int n_in,
                              void* d_out, int out_size) {
    const float* x     = (const float*)d_in[0];
    const float* ln_g  = (const float*)d_in[1];
    const float* ln_b  = (const float*)d_in[2];
    const float* W_ih0 = (const float*)d_in[3];
    const float* W_hh0 = (const float*)d_in[4];
    const float* b0    = (const float*)d_in[5];
    const float* W_ih1 = (const float*)d_in[6];
    const float* W_hh1 = (const float*)d_in[7];
    const float* b1    = (const float*)d_in[8];
    const float* Wp1   = (const float*)d_in[9];
    const float* bp1   = (const float*)d_in[10];
    const float* Wp2   = (const float*)d_in[11];
    const float* bp2   = (const float*)d_in[12];
    float* out = (float*)d_out;

    float *xn, *xg, *h0;
    bf16 *ah, *al, *wh0, *wl0, *wh1, *wl1;
    cudaGetSymbolAddress((void**)&xn,  g_xn);
    cudaGetSymbolAddress((void**)&xg,  g_xg);
    cudaGetSymbolAddress((void**)&h0,  g_h0);
    cudaGetSymbolAddress((void**)&ah,  g_ah);
    cudaGetSymbolAddress((void**)&al,  g_al);
    cudaGetSymbolAddress((void**)&wh0, g_wh0);
    cudaGetSymbolAddress((void**)&wl0, g_wl0);
    cudaGetSymbolAddress((void**)&wh1, g_wh1);
    cudaGetSymbolAddress((void**)&wl1, g_wl1);

    cudaFuncSetAttribute(mma_gemm_kernel<KP0>, cudaFuncAttributeMaxDynamicSharedMemorySize, GEMM_SMEM);
    cudaFuncSetAttribute(mma_gemm_kernel<KP1>, cudaFuncAttributeMaxDynamicSharedMemorySize, GEMM_SMEM);
    cudaFuncSetAttribute(lstm_cluster_kernel,  cudaFuncAttributeMaxDynamicSharedMemorySize, LSTM_SMEM_BYTES);

    wsplit_kernel<D_, KP0><<<(G_ * KP0 + 255) / 256, 256>>>(W_ih0, wh0, wl0);
    wsplit_kernel<H_, KP1><<<(G_ * KP1 + 255) / 256, 256>>>(W_ih1, wh1, wl1);
    ln_split_kernel<<<M_ / 8, 256>>>(x, ln_g, ln_b, ah, al);

    mma_gemm_kernel<KP0><<<dim3(8, M_ / 128), 256, GEMM_SMEM>>>(ah, al, wh0, wl0, b0, xg);
    lstm_cluster_kernel<<<128, 256, LSTM_SMEM_BYTES>>>(xg, W_hh0, h0);

    hsplit_kernel<<<(M_ * H_) / 512, 256>>>(h0, ah, al);
    mma_gemm_kernel<KP1><<<dim3(8, M_ / 128), 256, GEMM_SMEM>>>(ah, al, wh1, wl1, b1, xg);
    lstm_cluster_kernel<<<128, 256, LSTM_SMEM_BYTES>>>(xg, W_hh1, xn);

    proj_kernel<<<M_ / 32, 256>>>(xn, Wp1, bp1, Wp2, bp2, out);
}

// round 15
// speedup vs baseline: 2.2702x; 1.2149x over previous
#include <cuda_runtime.h>
#include <cuda_bf16.h>
#include <stdint.h>
#include <math.h>

#define B_ 1024
#define T_ 250
#define D_ 158
#define H_ 128
#define G_ 512
#define M_ (B_*T_)
#define P_ 64
#define O_ 22
#define KP0 192
#define KP1 128

typedef unsigned long long ull;
typedef __nv_bfloat16 bf16;

// ---------------- scratch ----------------
__device__ float g_xn[(size_t)M_ * H_];        // layer-1 h fp32 (batch-major)
__device__ float g_h0[(size_t)M_ * H_];        // layer-0 h fp32
__device__ float g_xg[(size_t)M_ * G_];        // gate preactivations fp32; later reused as p[M][64]
__device__ bf16  g_ah[(size_t)M_ * KP0];
__device__ bf16  g_al[(size_t)M_ * KP0];
__device__ bf16  g_wh0[G_ * KP0], g_wl0[G_ * KP0];
__device__ bf16  g_wh1[G_ * KP1], g_wl1[G_ * KP1];
__device__ bf16  g_wph[P_ * H_],  g_wpl[P_ * H_];

// ---------------- helpers ----------------
__device__ __forceinline__ void fma2(ull& d, ull a, ull b, ull c) {
    asm("fma.rn.f32x2 %0, %1, %2, %3;" : "=l"(d) : "l"(a), "l"(b), "l"(c));
}
__device__ __forceinline__ ull pack2(float a, float b) {
    ull r; asm("mov.b64 %0, {%1,%2};" : "=l"(r) : "f"(a), "f"(b)); return r;
}
__device__ __forceinline__ float2 upk2(ull v) {
    float2 r; asm("mov.b64 {%0,%1}, %2;" : "=f"(r.x), "=f"(r.y) : "l"(v)); return r;
}
__device__ __forceinline__ uint32_t s2u(const void* p) {
    return (uint32_t)__cvta_generic_to_shared(p);
}
__device__ __forceinline__ void st_remote_u64(uint32_t laddr, uint32_t peer, ull v) {
    uint32_t r;
    asm volatile("mapa.shared::cluster.u32 %0, %1, %2;" : "=r"(r) : "r"(laddr), "r"(peer));
    asm volatile("st.shared::cluster.b64 [%0], %1;" :: "r"(r), "l"(v) : "memory");
}
__device__ __forceinline__ void cpasync16(uint32_t saddr, const void* g) {
    asm volatile("cp.async.cg.shared.global [%0], [%1], 16;" :: "r"(saddr), "l"(g));
}
#define CP_COMMIT() asm volatile("cp.async.commit_group;" ::: "memory")
#define CP_WAIT(n)  asm volatile("cp.async.wait_group %0;" :: "n"(n) : "memory")

__device__ __forceinline__ void ldsm4(uint32_t* r, uint32_t addr) {
    asm volatile("ldmatrix.sync.aligned.m8n8.x4.shared.b16 {%0,%1,%2,%3}, [%4];"
                 : "=r"(r[0]), "=r"(r[1]), "=r"(r[2]), "=r"(r[3]) : "r"(addr));
}
__device__ __forceinline__ void mma16816(float* d, const uint32_t* a, const uint32_t* b) {
    asm volatile("mma.sync.aligned.m16n8k16.row.col.f32.bf16.bf16.f32 "
                 "{%0,%1,%2,%3}, {%4,%5,%6,%7}, {%8,%9}, {%0,%1,%2,%3};"
                 : "+f"(d[0]), "+f"(d[1]), "+f"(d[2]), "+f"(d[3])
                 : "r"(a[0]), "r"(a[1]), "r"(a[2]), "r"(a[3]), "r"(b[0]), "r"(b[1]));
}

__device__ __forceinline__ float sigm_(float x) { return 1.f / (1.f + __expf(-x)); }
__device__ __forceinline__ float tanh_fast(float x) {
    float a = fabsf(x);
    float e = __expf(a + a);
    float t = 1.f - 2.f / (e + 1.f);
    return copysignf(t, x);
}
__device__ __forceinline__ void bf_split(float v, bf16& h, bf16& l) {
    h = __float2bfloat16_rn(v);
    l = __float2bfloat16_rn(v - __bfloat162float(h));
}

// ---------------- W split: [ROWS][K] fp32 -> hi/lo bf16 [ROWS][KPAD] ----------------
template <int K, int KPAD, int ROWS>
__global__ void wsplit_kernel(const float* __restrict__ W, bf16* __restrict__ wh,
                              bf16* __restrict__ wl) {
    int idx = blockIdx.x * 256 + threadIdx.x;
    if (idx >= ROWS * KPAD) return;
    int g = idx / KPAD, k = idx - g * KPAD;
    float v = (k < K) ? W[g * K + k] : 0.f;
    bf16 h, l; bf_split(v, h, l);
    wh[idx] = h; wl[idx] = l;
}

// ---------------- h split: [M][128] fp32 -> hi/lo bf16 ----------------
__global__ void __launch_bounds__(256) hsplit_kernel(const float* __restrict__ h,
                                                     bf16* __restrict__ ah,
                                                     bf16* __restrict__ al) {
    size_t idx = (size_t)blockIdx.x * 512 + threadIdx.x * 2;
    float2 v = *(const float2*)(h + idx);
    bf16 h0, l0, h1, l1;
    bf_split(v.x, h0, l0);
    bf_split(v.y, h1, l1);
    __nv_bfloat162 hh; hh.x = h0; hh.y = h1;
    __nv_bfloat162 ll; ll.x = l0; ll.y = l1;
    *(__nv_bfloat162*)(ah + idx) = hh;
    *(__nv_bfloat162*)(al + idx) = ll;
}

// ---------------- LayerNorm -> bf16 hi/lo, batch-major [b*T+t][KP0] ----------------
__global__ void __launch_bounds__(256) ln_split_kernel(const float* __restrict__ x,
                                                       const float* __restrict__ gamma,
                                                       const float* __restrict__ beta,
                                                       bf16* __restrict__ ah,
                                                       bf16* __restrict__ al) {
    int row = blockIdx.x * 8 + (threadIdx.x >> 5);
    int lane = threadIdx.x & 31;
    const float* xr = x + (size_t)row * D_;
    float v[5];
    float s = 0.f, s2 = 0.f;
#pragma unroll
    for (int i = 0; i < 5; i++) {
        int k = lane + 32 * i;
        v[i] = (k < D_) ? xr[k] : 0.f;
        s += v[i];
        s2 = fmaf(v[i], v[i], s2);
    }
#pragma unroll
    for (int o = 16; o; o >>= 1) {
        s  += __shfl_xor_sync(0xffffffffu, s, o);
        s2 += __shfl_xor_sync(0xffffffffu, s2, o);
    }
    float mu  = s * (1.f / D_);
    float var = s2 * (1.f / D_) - mu * mu;
    float inv = rsqrtf(var + 1e-5f);
    size_t orow = (size_t)row * KP0;
#pragma unroll
    for (int i = 0; i < 5; i++) {
        int k = lane + 32 * i;
        float xv = (k < D_) ? ((v[i] - mu) * inv * gamma[k] + beta[k]) : 0.f;
        bf16 h, l; bf_split(xv, h, l);
        if (k < 160) { ah[orow + k] = h; al[orow + k] = l; }
    }
    ah[orow + 160 + lane] = __float2bfloat16_rn(0.f);
    al[orow + 160 + lane] = __float2bfloat16_rn(0.f);
}

// ---------------- split-bf16 mma.sync GEMM, cp.async 2-stage pipeline ----------------
// CTA 128m x 64n, 8 warps (4m x 2n). Stage = {sAh 16K, sAl 16K, sWh 8K, sWl 8K} = 48KB.
#define STAGE_B 49152
#define GEMM_SMEM (2 * STAGE_B)
template <int KPAD, int RELU, int CSTR>
__global__ void __launch_bounds__(256) mma_gemm_kernel(const bf16* __restrict__ Ah,
                                                       const bf16* __restrict__ Al,
                                                       const bf16* __restrict__ Wh,
                                                       const bf16* __restrict__ Wl,
                                                       const float* __restrict__ bias,
                                                       float* __restrict__ C) {
    extern __shared__ char sm2[];
    constexpr int NC = KPAD / 64;

    int tid = threadIdx.x;
    int wid = tid >> 5, lane = tid & 31;
    int wm = wid & 3, wn = wid >> 2;
    int m0 = blockIdx.y * 128, n0 = blockIdx.x * 64;
    uint32_t sbase = s2u(sm2);

    float acc[2][4][4];
#pragma unroll
    for (int i = 0; i < 2; i++)
#pragma unroll
        for (int j = 0; j < 4; j++)
#pragma unroll
            for (int q = 0; q < 4; q++) acc[i][j][q] = 0.f;

    float2 bv[4];
#pragma unroll
    for (int nt = 0; nt < 4; nt++) {
        int col = n0 + wn * 32 + nt * 8 + 2 * (lane & 3);
        bv[nt] = make_float2(bias[col], bias[col + 1]);
    }

    int a_row = (lane & 7) + ((lane >> 3) & 1) * 8;
    int a_chk = lane >> 4;
    int w_row = (lane & 7) + (lane >> 4) * 8;
    int w_chk = (lane >> 3) & 1;

    // chunk loader via cp.async (swizzled layout identical to validated R14 fill)
    auto load_chunk = [&](int kc, int st) {
        uint32_t bAh = sbase + st * STAGE_B;
        uint32_t bAl = bAh + 16384;
        uint32_t bWh = bAh + 32768;
        uint32_t bWl = bAh + 40960;
        const bf16* gA0 = Ah + (size_t)m0 * KPAD + kc * 64;
        const bf16* gA1 = Al + (size_t)m0 * KPAD + kc * 64;
#pragma unroll
        for (int i = tid; i < 1024; i += 256) {
            int row = i >> 3, cc = i & 7;
            int phys = cc ^ (row & 7);
            uint32_t so = (uint32_t)(row * 128 + phys * 16);
            cpasync16(bAh + so, gA0 + (size_t)row * KPAD + cc * 8);
            cpasync16(bAl + so, gA1 + (size_t)row * KPAD + cc * 8);
        }
        const bf16* gW0 = Wh + (size_t)n0 * KPAD + kc * 64;
        const bf16* gW1 = Wl + (size_t)n0 * KPAD + kc * 64;
#pragma unroll
        for (int i = tid; i < 512; i += 256) {
            int row = i >> 3, cc = i & 7;
            int phys = cc ^ (row & 7);
            uint32_t so = (uint32_t)(row * 128 + phys * 16);
            cpasync16(bWh + so, gW0 + (size_t)row * KPAD + cc * 8);
            cpasync16(bWl + so, gW1 + (size_t)row * KPAD + cc * 8);
        }
    };

    load_chunk(0, 0); CP_COMMIT();
    if (NC > 1) { load_chunk(1, 1); CP_COMMIT(); }

    for (int kc = 0; kc < NC; kc++) {
        if (kc + 1 < NC) CP_WAIT(1); else CP_WAIT(0);
        __syncthreads();

        uint32_t bAh = sbase + (kc & 1) * STAGE_B;
        uint32_t bAl = bAh + 16384;
        uint32_t bWh = bAh + 32768;
        uint32_t bWl = bAh + 40960;
#pragma unroll
        for (int ks = 0; ks < 4; ks++) {
            int cb = ks * 2;
            uint32_t ah[2][4], al[2][4], wh[4][2], wl[4][2];
#pragma unroll
            for (int mt = 0; mt < 2; mt++) {
                int row = wm * 32 + mt * 16 + a_row;
                int chk = cb + a_chk;
                uint32_t off = (uint32_t)(row * 64 + (chk ^ (row & 7)) * 8) * 2u;
                ldsm4(ah[mt], bAh + off);
                ldsm4(al[mt], bAl + off);
            }
#pragma unroll
            for (int g = 0; g < 2; g++) {
                int row = wn * 32 + g * 16 + w_row;
                int chk = cb + w_chk;
                uint32_t off = (uint32_t)(row * 64 + (chk ^ (row & 7)) * 8) * 2u;
                uint32_t rh[4], rl[4];
                ldsm4(rh, bWh + off);
                ldsm4(rl, bWl + off);
                wh[2 * g][0] = rh[0]; wh[2 * g][1] = rh[1];
                wh[2 * g + 1][0] = rh[2]; wh[2 * g + 1][1] = rh[3];
                wl[2 * g][0] = rl[0]; wl[2 * g][1] = rl[1];
                wl[2 * g + 1][0] = rl[2]; wl[2 * g + 1][1] = rl[3];
            }
#pragma unroll
            for (int mt = 0; mt < 2; mt++)
#pragma unroll
                for (int nt = 0; nt < 4; nt++) {
                    mma16816(acc[mt][nt], ah[mt], wh[nt]);
                    mma16816(acc[mt][nt], ah[mt], wl[nt]);
                    mma16816(acc[mt][nt], al[mt], wh[nt]);
                }
        }
        __syncthreads();
        if (kc + 2 < NC) { load_chunk(kc + 2, kc & 1); CP_COMMIT(); }
    }

#pragma unroll
    for (int mt = 0; mt < 2; mt++) {
        int row = m0 + wm * 32 + mt * 16 + (lane >> 2);
#pragma unroll
        for (int nt = 0; nt < 4; nt++) {
            int col = n0 + wn * 32 + nt * 8 + 2 * (lane & 3);
            float* p = C + (size_t)row * CSTR + col;
            float v0 = acc[mt][nt][0] + bv[nt].x, v1 = acc[mt][nt][1] + bv[nt].y;
            float v2 = acc[mt][nt][2] + bv[nt].x, v3 = acc[mt][nt][3] + bv[nt].y;
            if (RELU) {
                v0 = v0 > 0.f ? v0 : 0.f; v1 = v1 > 0.f ? v1 : 0.f;
                v2 = v2 > 0.f ? v2 : 0.f; v3 = v3 > 0.f ? v3 : 0.f;
            }
            *(float2*)p = make_float2(v0, v1);
            *(float2*)(p + 8 * CSTR) = make_float2(v2, v3);
        }
    }
}

// ---------------- clustered LSTM v2: thread = 2 gates x 8 rows, k-pair FFMA2 ----------------
// smem: ws [64 kp][128 gu] ulonglong2 (128KB) + hs [2][64 kp][18 rows] ull (18432B)
//       + gs [16][258] f32 (16512B) = 166016 B
#define LSTM2_SMEM (131072 + 18432 + 16512)

__global__ void __launch_bounds__(256) __cluster_dims__(2, 1, 1)
lstm2_kernel(const float* __restrict__ xg,
             const float* __restrict__ Whh,
             float* __restrict__ hout) {
    extern __shared__ ull sm[];
    ull*   ws = sm;                            // [64][128] ulonglong2 = 16384 ull
    ull*   hs = sm + 16384;                    // [2][64][18] = 2304 ull
    float* gs = (float*)(sm + 16384 + 2304);   // [16][258]

    int tid = threadIdx.x;
    uint32_t crank;
    asm("mov.u32 %0, %%cluster_ctarank;" : "=r"(crank));
    int c = (int)crank;
    int b0 = (blockIdx.x >> 1) * 16;

    // ws fill: ws2[kp][gu] = ((W[g2u][2kp],W[g2u][2kp+1]), (W[g2u+1][2kp],W[g2u+1][2kp+1]))
    for (int idx = tid; idx < 16384; idx += 256) {
        int u2 = idx >> 1, e = idx & 1;
        int kp = u2 >> 7, gu = u2 & 127;
        int gate = 2 * gu + e;
        int q = gate >> 6, jj = gate & 63;
        int gg = 128 * q + 64 * c + jj;
        ws[idx] = pack2(Whh[gg * 128 + 2 * kp], Whh[gg * 128 + 2 * kp + 1]);
    }
    for (int i = tid; i < 2304; i += 256) hs[i] = 0ull;
    __syncthreads();
    asm volatile("barrier.cluster.arrive.aligned;" ::: "memory");
    asm volatile("barrier.cluster.wait.aligned;" ::: "memory");

    // phase-A mapping: rh = row half (8 rows), gu = gate unit (gates 2gu, 2gu+1)
    int rh = tid >> 7;
    int gu = tid & 127;
    int ga = 2 * gu;
    int q = ga >> 6, j = ga & 63;
    int gg = 128 * q + 64 * c + j;             // 2 consecutive global gates

    // phase-B mapping (R14-identical gate math)
    int wB = tid >> 5;
    int l  = tid & 31;
    int l2 = 2 * l;
    float2 cst[2] = {{0.f, 0.f}, {0.f, 0.f}};

    uint32_t hs_u32 = s2u(hs);
    const float* xgp[8];
#pragma unroll
    for (int r = 0; r < 8; r++)
        xgp[r] = xg + (size_t)(b0 + rh * 8 + r) * T_ * G_ + gg;

    float2 pref[8];
#pragma unroll
    for (int r = 0; r < 8; r++) pref[r] = *(const float2*)(xgp[r]);

    const ulonglong2* wp = (const ulonglong2*)ws + gu;

    for (int t = 0; t < T_; t++) {
        int par = t & 1;
        ull acc0[8], acc1[8];
#pragma unroll
        for (int r = 0; r < 8; r++) {
            acc0[r] = pack2(pref[r].x, 0.f);
            acc1[r] = pack2(pref[r].y, 0.f);
        }
        int tn = (t + 1 < T_) ? (t + 1) : t;
#pragma unroll
        for (int r = 0; r < 8; r++)
            pref[r] = *(const float2*)(xgp[r] + (size_t)tn * G_);

        const ull* hp = hs + par * 1152 + rh * 8;
#pragma unroll 2
        for (int kp = 0; kp < 64; kp++) {
            ulonglong2 w2 = wp[kp * 128];
            const ulonglong2* hk = (const ulonglong2*)(hp + kp * 18);
            ulonglong2 h01 = hk[0], h23 = hk[1], h45 = hk[2], h67 = hk[3];
            fma2(acc0[0], (ull)w2.x, (ull)h01.x, acc0[0]);
            fma2(acc1[0], (ull)w2.y, (ull)h01.x, acc1[0]);
            fma2(acc0[1], (ull)w2.x, (ull)h01.y, acc0[1]);
            fma2(acc1[1], (ull)w2.y, (ull)h01.y, acc1[1]);
            fma2(acc0[2], (ull)w2.x, (ull)h23.x, acc0[2]);
            fma2(acc1[2], (ull)w2.y, (ull)h23.x, acc1[2]);
            fma2(acc0[3], (ull)w2.x, (ull)h23.y, acc0[3]);
            fma2(acc1[3], (ull)w2.y, (ull)h23.y, acc1[3]);
            fma2(acc0[4], (ull)w2.x, (ull)h45.x, acc0[4]);
            fma2(acc1[4], (ull)w2.y, (ull)h45.x, acc1[4]);
            fma2(acc0[5], (ull)w2.x, (ull)h45.y, acc0[5]);
            fma2(acc1[5], (ull)w2.y, (ull)h45.y, acc1[5]);
            fma2(acc0[6], (ull)w2.x, (ull)h67.x, acc0[6]);
            fma2(acc1[6], (ull)w2.y, (ull)h67.x, acc1[6]);
            fma2(acc0[7], (ull)w2.x, (ull)h67.y, acc0[7]);
            fma2(acc1[7], (ull)w2.y, (ull)h67.y, acc1[7]);
        }
#pragma unroll
        for (int r = 0; r < 8; r++) {
            float2 p0 = upk2(acc0[r]);
            float2 p1 = upk2(acc1[r]);
            *(float2*)&gs[(rh * 8 + r) * 258 + ga] = make_float2(p0.x + p0.y, p1.x + p1.y);
        }
        __syncthreads();

        // phase B (gate order i, f, g, o); h stored [kp][row] for phase A's k-pair reads
        ull* hnew = hs + (par ^ 1) * 1152;
        uint32_t hnew_u32 = hs_u32 + (uint32_t)((par ^ 1) * 1152) * 8u;
#pragma unroll
        for (int s = 0; s < 2; s++) {
            int row = wB + 8 * s;
            float2 gi = *(float2*)&gs[row * 258 + l2];
            float2 gf = *(float2*)&gs[row * 258 + 64 + l2];
            float2 gG = *(float2*)&gs[row * 258 + 128 + l2];
            float2 go = *(float2*)&gs[row * 258 + 192 + l2];
            float2 cc = cst[s];
            cc.x = sigm_(gf.x) * cc.x + sigm_(gi.x) * tanh_fast(gG.x);
            cc.y = sigm_(gf.y) * cc.y + sigm_(gi.y) * tanh_fast(gG.y);
            float h0v = sigm_(go.x) * tanh_fast(cc.x);
            float h1v = sigm_(go.y) * tanh_fast(cc.y);
            cst[s] = cc;
            int kpg = 32 * c + l;              // global k-pair for units (64c+2l, 64c+2l+1)
            ull pv = pack2(h0v, h1v);
            hnew[kpg * 18 + row] = pv;
            st_remote_u64(hnew_u32 + (uint32_t)(kpg * 18 + row) * 8u, (uint32_t)(c ^ 1), pv);
            int jj = 64 * c + l2;
            *(float2*)&hout[((size_t)(b0 + row) * T_ + t) * H_ + jj] = make_float2(h0v, h1v);
        }
        asm volatile("barrier.cluster.arrive.aligned;" ::: "memory");
        asm volatile("barrier.cluster.wait.aligned;" ::: "memory");
    }
}

// ---------------- proj2: out[M,22] = p[M,64] @ Wp2^T + b2 ----------------
__global__ void __launch_bounds__(256) proj2_kernel(const float* __restrict__ p,
                                                    const float* __restrict__ Wp2,
                                                    const float* __restrict__ bp2,
                                                    float* __restrict__ out) {
    __shared__ float ps[32][68];
    __shared__ float w2t[64][22];
    __shared__ float b2s[22];
    int tid = threadIdx.x;

    for (int i = tid; i < O_ * P_; i += 256) { int oo = i >> 6, kk = i & 63; w2t[kk][oo] = Wp2[i]; }
    if (tid < O_) b2s[tid] = bp2[tid];
    size_t row0 = (size_t)blockIdx.x * 32;
    for (int i = tid; i < 512; i += 256) {
        int rr = i >> 4, cc = i & 15;
        *(float4*)&ps[rr][cc * 4] = *(const float4*)(p + (row0 + rr) * P_ + cc * 4);
    }
    __syncthreads();

    for (int idx = tid; idx < 32 * O_; idx += 256) {
        int rr = idx / O_;
        int oo = idx - rr * O_;
        float s = b2s[oo];
#pragma unroll
        for (int k = 0; k < P_; k++) s = fmaf(ps[rr][k], w2t[k][oo], s);
        out[(row0 + rr) * O_ + oo] = s;
    }
}

// ---------------- launch ----------------
extern "C" void kernel_launch(void* const* d_in, const int* in_sizes, int n_in,
                              void* d_out, int out_size) {
    const float* x     = (const float*)d_in[0];
    const float* ln_g  = (const float*)d_in[1];
    const float* ln_b  = (const float*)d_in[2];
    const float* W_ih0 = (const float*)d_in[3];
    const float* W_hh0 = (const float*)d_in[4];
    const float* b0    = (const float*)d_in[5];
    const float* W_ih1 = (const float*)d_in[6];
    const float* W_hh1 = (const float*)d_in[7];
    const float* b1    = (const float*)d_in[8];
    const float* Wp1   = (const float*)d_in[9];
    const float* bp1   = (const float*)d_in[10];
    const float* Wp2   = (const float*)d_in[11];
    const float* bp2   = (const float*)d_in[12];
    float* out = (float*)d_out;

    float *xn, *xg, *h0;
    bf16 *ah, *al, *wh0, *wl0, *wh1, *wl1, *wph, *wpl;
    cudaGetSymbolAddress((void**)&xn,  g_xn);
    cudaGetSymbolAddress((void**)&xg,  g_xg);
    cudaGetSymbolAddress((void**)&h0,  g_h0);
    cudaGetSymbolAddress((void**)&ah,  g_ah);
    cudaGetSymbolAddress((void**)&al,  g_al);
    cudaGetSymbolAddress((void**)&wh0, g_wh0);
    cudaGetSymbolAddress((void**)&wl0, g_wl0);
    cudaGetSymbolAddress((void**)&wh1, g_wh1);
    cudaGetSymbolAddress((void**)&wl1, g_wl1);
    cudaGetSymbolAddress((void**)&wph, g_wph);
    cudaGetSymbolAddress((void**)&wpl, g_wpl);
    float* p = xg;   // reuse gate buffer for p[M][64] after LSTM1 consumes gates

    cudaFuncSetAttribute(mma_gemm_kernel<KP0, 0, G_>, cudaFuncAttributeMaxDynamicSharedMemorySize, GEMM_SMEM);
    cudaFuncSetAttribute(mma_gemm_kernel<KP1, 0, G_>, cudaFuncAttributeMaxDynamicSharedMemorySize, GEMM_SMEM);
    cudaFuncSetAttribute(mma_gemm_kernel<KP1, 1, P_>, cudaFuncAttributeMaxDynamicSharedMemorySize, GEMM_SMEM);
    cudaFuncSetAttribute(lstm2_kernel, cudaFuncAttributeMaxDynamicSharedMemorySize, LSTM2_SMEM);

    wsplit_kernel<D_, KP0, G_><<<(G_ * KP0 + 255) / 256, 256>>>(W_ih0, wh0, wl0);
    wsplit_kernel<H_, KP1, G_><<<(G_ * KP1 + 255) / 256, 256>>>(W_ih1, wh1, wl1);
    wsplit_kernel<H_, KP1, P_><<<(P_ * KP1 + 255) / 256, 256>>>(Wp1, wph, wpl);
    ln_split_kernel<<<M_ / 8, 256>>>(x, ln_g, ln_b, ah, al);

    mma_gemm_kernel<KP0, 0, G_><<<dim3(8, M_ / 128), 256, GEMM_SMEM>>>(ah, al, wh0, wl0, b0, xg);
    lstm2_kernel<<<128, 256, LSTM2_SMEM>>>(xg, W_hh0, h0);

    hsplit_kernel<<<(M_ * H_) / 512, 256>>>(h0, ah, al);
    mma_gemm_kernel<KP1, 0, G_><<<dim3(8, M_ / 128), 256, GEMM_SMEM>>>(ah, al, wh1, wl1, b1, xg);
    lstm2_kernel<<<128, 256, LSTM2_SMEM>>>(xg, W_hh1, xn);

    hsplit_kernel<<<(M_ * H_) / 512, 256>>>(xn, ah, al);
    mma_gemm_kernel<KP1, 1, P_><<<dim3(1, M_ / 128), 256, GEMM_SMEM>>>(ah, al, wph, wpl, bp1, p);
    proj2_kernel<<<M_ / 32, 256>>>(p, Wp2, bp2, out);
}